// round 11
// baseline (speedup 1.0000x reference)
#include <cuda_runtime.h>
#include <stdint.h>
#include <math.h>

#define NKPT 21
#define NANCH 12
#define BMAX 32
#define MAXA (12*128*128)
#define BSPLIT 4
#define CTILE 64
#define CTHREADS 512

__constant__ float c_ref[NKPT*2] = {
 213.33335876464844f, 124.50563049316406f,
 190.504638671875f,   115.11840057373047f,
 169.9791717529297f,  101.77180480957031f,
 146.72341918945312f,  96.25749206542969f,
 128.86770629882812f,  87.2344970703125f,
 150.34292602539062f, 101.61070251464844f,
 119.29926300048828f,  98.73982238769531f,
 100.03463745117188f,  99.74459838867188f,
  82.62400817871094f, 101.2509536743164f,
 148.91049194335938f, 112.71517181396484f,
 114.37303161621094f, 113.20121002197266f,
  91.90096282958984f, 116.49812316894531f,
  74.75020599365234f, 119.37875366210938f,
 149.59658813476562f, 124.09295654296875f,
 119.72419738769531f, 126.36898040771484f,
  99.59107208251953f, 129.40196228027344f,
  82.82524108886719f, 131.584228515625f,
 154.55911254882812f, 135.07681274414062f,
 133.8833770751953f,  140.85983276367188f,
 120.45906066894531f, 145.40306091308594f,
 106.21541595458984f, 150.072265625f
};

// (float)cos/sin of 0,90,180,270 deg (double-computed, cast)
__constant__ float c_trig[8] = {
 1.0f, 0.0f,
 6.123233995736766e-17f, 1.0f,
 -1.0f, 1.2246467991473532e-16f,
 -1.8369701987210297e-16f, -1.0f
};

// Per-(b,a) decision: 0=neg(inside), 1=left, 2=right, 3=outside.
__device__ uint8_t g_dec[(size_t)BMAX * MAXA];

__device__ __forceinline__ float ex2f(float x) {
    float y; asm("ex2.approx.f32 %0, %1;" : "=f"(y) : "f"(x)); return y;
}

__device__ __forceinline__ void ref_center(float& cx, float& cy) {
    float sx = 0.f, sy = 0.f;
    #pragma unroll
    for (int k = 0; k < NKPT; k++) { sx += c_ref[2*k]; sy += c_ref[2*k+1]; }
    cx = sx / 21.0f; cy = sy / 21.0f;
}

__device__ __forceinline__ float2 anchor_pt(int a, int k, int feat_w, int feat_h,
                                            float cx, float cy) {
    int j   = a % NANCH;
    int pos = a / NANCH;
    int ix  = pos % feat_w;
    int iy  = pos / feat_w;
    float shx = (float)((double)ix * (256.0 / (double)feat_w));
    float shy = (float)((double)iy * (256.0 / (double)feat_h));
    int si = j >> 2, oi = j & 3;
    float sc  = (si == 0) ? 0.25f : ((si == 1) ? 0.5f : 1.0f);
    float cth = c_trig[2*oi], sth = c_trig[2*oi+1];
    float vx = c_ref[2*k]   - cx;
    float vy = c_ref[2*k+1] - cy;
    return make_float2(cx + sc * (vx*cth - vy*sth) + shx,
                       cy + sc * (vx*sth + vy*cth) + shy);
}

// -----------------------------------------------------------------------------
// Phase A: PURE decision kernel. 128 anchors/block, blockIdx.y = 4 batches.
// Pose in registers -> inside -> OKS -> g_dec. No global anchor/inside writes.
// -----------------------------------------------------------------------------
__global__ void __launch_bounds__(128) phaseA_kernel(
    const float* __restrict__ gt,   // [B,2,21,3]
    const int*   __restrict__ ht,   // [B,2]
    const int*   __restrict__ fhp,
    const int*   __restrict__ fwp,
    int B, int A)
{
    __shared__ float s_gxy[BSPLIT*2*42];   // poisoned xy
    __shared__ float s_nc[BSPLIT*2];
    __shared__ float s_nvinv[BSPLIT*2];
    __shared__ int   s_ht[BSPLIT*2];

    const int tid = threadIdx.x;
    const int by  = blockIdx.y;
    const int bbase  = by * BSPLIT;
    const int bcount = min(BSPLIT, B - bbase);

    int feat_w, feat_h;
    if (fwp) { feat_w = *fwp; feat_h = *fhp; }
    else {
        int pos = A / NANCH;
        feat_w = (int)rintf(sqrtf((float)pos));
        feat_h = pos / feat_w;
    }

    // stage packed gt xy, poisoning invisible keypoints (vis<=0 -> 1e19)
    const int ng = bcount * 84;
    for (int i = tid; i < ng; i += 128) {
        int b2 = i / 42, e = i - b2*42;
        int k = e >> 1;
        const float* base = gt + (size_t)(bbase*2 + b2)*63 + 3*k;
        float v   = base[e & 1];
        float vis = base[2];
        s_gxy[i] = (vis > 0.f) ? v : 1e19f;
    }
    if (tid < bcount*2) s_ht[tid] = ht[bbase*2 + tid];
    __syncthreads();

    if (tid < bcount*2) {
        const float* g = gt + (size_t)(bbase*2 + tid)*63;
        float xmn = 3.4e38f, xmx = -3.4e38f, ymn = 3.4e38f, ymx = -3.4e38f, nv = 0.f;
        #pragma unroll
        for (int k = 0; k < NKPT; k++) {
            float x = g[3*k], y = g[3*k+1];
            xmn = fminf(xmn, x); xmx = fmaxf(xmx, x);
            ymn = fminf(ymn, y); ymx = fmaxf(ymx, y);
            if (g[3*k+2] > 0.f) nv += 1.f;
        }
        float s2 = fmaxf((xmx - xmn) * (ymx - ymn), 1.f);
        s_nc[tid]    = -1.442695040888963f / (2.f * s2 * 0.01f);
        s_nvinv[tid] = 1.f / fmaxf(nv, 1.f);
    }
    __syncthreads();

    const int a = blockIdx.x * 128 + tid;
    if (a >= A) return;

    float cx, cy;
    ref_center(cx, cy);

    float ax[NKPT], ay[NKPT];
    bool inside = true;
    #pragma unroll
    for (int k = 0; k < NKPT; k++) {
        float2 p = anchor_pt(a, k, feat_w, feat_h, cx, cy);
        ax[k] = p.x; ay[k] = p.y;
        inside = inside && (p.x >= 0.f) && (p.y >= 0.f) && (p.x < 256.f) && (p.y < 256.f);
    }

    if (!inside) {
        for (int bl = 0; bl < bcount; bl++)
            g_dec[(size_t)(bbase + bl)*A + a] = 3;
    } else {
        for (int bl = 0; bl < bcount; bl++) {
            const float2* g0 = (const float2*)(s_gxy + bl*84);
            const float2* g1 = g0 + NKPT;
            float nc0 = s_nc[2*bl], nc1 = s_nc[2*bl+1];
            float acc0 = 0.f, acc1 = 0.f;
            #pragma unroll
            for (int k = 0; k < NKPT; k++) {
                float2 p0 = g0[k];
                float dx0 = ax[k] - p0.x, dy0 = ay[k] - p0.y;
                acc0 += ex2f((dx0*dx0 + dy0*dy0) * nc0);
                float2 p1 = g1[k];
                float dx1 = ax[k] - p1.x, dy1 = ay[k] - p1.y;
                acc1 += ex2f((dx1*dx1 + dy1*dy1) * nc1);
            }
            float sim0 = acc0 * s_nvinv[2*bl];
            float sim1 = acc1 * s_nvinv[2*bl+1];
            bool am0 = (sim0 >= sim1);
            float mxs = fmaxf(sim0, sim1);
            bool right = am0  && (mxs > 0.5f) && (s_ht[2*bl]   == 1);
            bool left  = !am0 && (mxs > 0.5f) && (s_ht[2*bl+1] == 1);
            g_dec[(size_t)(bbase + bl)*A + a] = right ? 2 : (left ? 1 : 0);
        }
    }
}

// -----------------------------------------------------------------------------
// Phase C: recomputes anchor tile in smem (no global anchor read), writes
// anchors + inside + labels + offsets. All-outside fast path; allneg per-b.
// -----------------------------------------------------------------------------
__global__ void __launch_bounds__(CTHREADS) phaseC_kernel(
    const float* __restrict__ gt,       // [B,2,21,3]
    const int*   __restrict__ fhp,
    const int*   __restrict__ fwp,
    float* __restrict__ anchors_out,    // [A,21,2]
    float* __restrict__ inside_out,     // [A]
    float* __restrict__ labels,         // [B,A,3]
    float* __restrict__ ofs,            // [B,A,21,2]
    int A, int B, int aligned4)
{
    __shared__ float  sA[CTILE*42];
    __shared__ float  sg[(BMAX*2+1)*42];         // + zero row at B*84
    __shared__ unsigned short sdw[BMAX*CTILE];
    __shared__ int s_allneg[BMAX];
    __shared__ int s_allout;
    __shared__ int s_in[CTILE];

    const int tid = threadIdx.x;
    const int a0  = blockIdx.x * CTILE;
    const int cnt = min(CTILE, A - a0);
    const int nfl = cnt * 42;
    const int nf4 = aligned4 ? (nfl >> 2) : 0;
    const int ng  = B * 84;
    const size_t bstride4 = ((size_t)A * 42) >> 2;

    int feat_w, feat_h;
    if (fwp) { feat_w = *fwp; feat_h = *fhp; }
    else {
        int pos = A / NANCH;
        feat_w = (int)rintf(sqrtf((float)pos));
        feat_h = pos / feat_w;
    }

    if (tid < CTILE) s_in[tid] = 1;
    __syncthreads();

    // ---- stage decision words (global, long latency) ----
    for (int i = tid; i < B*CTILE; i += CTHREADS) {
        int b = i >> 6, la = i & (CTILE-1);
        uint8_t d = (la < cnt) ? g_dec[(size_t)b*A + a0 + la] : (uint8_t)3;
        unsigned short r = (d == 2) ? (unsigned short)(b*84)
                         : (d == 1) ? (unsigned short)(b*84 + 42)
                         : (unsigned short)ng;
        sdw[i] = (unsigned short)(r | ((unsigned short)d << 12));
    }
    // ---- recompute anchor tile (FMA, overlaps the loads above) ----
    {
        float cx, cy;
        ref_center(cx, cy);
        for (int i = tid; i < cnt*NKPT; i += CTHREADS) {
            int al = i / NKPT, k = i - al*NKPT;
            float2 p = anchor_pt(a0 + al, k, feat_w, feat_h, cx, cy);
            sA[al*42 + 2*k]   = p.x;
            sA[al*42 + 2*k+1] = p.y;
            if (!((p.x >= 0.f) && (p.y >= 0.f) && (p.x < 256.f) && (p.y < 256.f)))
                s_in[al] = 0;                    // benign race: all write 0
        }
    }
    __syncthreads();

    // ---- flags ----
    if (tid < B) {
        int all0 = 1;
        #pragma unroll 8
        for (int la = 0; la < CTILE; la++)
            if ((sdw[tid*CTILE + la] >> 12) != 0) { all0 = 0; break; }
        s_allneg[tid] = all0;
    }
    if (tid == B) {
        int allo = 1;
        #pragma unroll 8
        for (int la = 0; la < CTILE; la++)
            if ((sdw[la] >> 12) != 3) { allo = 0; break; }
        s_allout = allo;
    }

    // ---- anchors + inside (common to both paths) ----
    if (tid < cnt)
        __stcs(&inside_out[a0 + tid], s_in[tid] ? 1.f : 0.f);
    {
        float4* op = (float4*)(anchors_out + (size_t)a0*42);
        for (int f = tid; f < nf4; f += CTHREADS) __stcs(op + f, ((const float4*)sA)[f]);
        for (int o = (nf4 << 2) + tid; o < nfl; o += CTHREADS)
            anchors_out[(size_t)a0*42 + o] = sA[o];
    }
    __syncthreads();

    // ---- ALL-OUTSIDE fast path: labels=-1, offsets=0 ----
    if (s_allout) {
        const float4 m1 = make_float4(-1.f, -1.f, -1.f, -1.f);
        const float4 z  = make_float4(0.f, 0.f, 0.f, 0.f);
        if (aligned4 && cnt == CTILE) {
            const int lf4 = (CTILE*3) >> 2;
            for (int b = 0; b < B; b++) {
                float4* lp = (float4*)(labels + ((size_t)b*A + a0)*3);
                for (int f = tid; f < lf4; f += CTHREADS) __stcs(lp + f, m1);
            }
        } else {
            for (int b = 0; b < B; b++)
                for (int o = tid; o < cnt*3; o += CTHREADS)
                    labels[((size_t)b*A + a0)*3 + o] = -1.f;
        }
        if (aligned4) {
            for (int b = 0; b < B; b++) {
                float4* op = (float4*)(ofs + ((size_t)b*A + a0)*42);
                for (int f = tid; f < nf4; f += CTHREADS) __stcs(op + f, z);
            }
        } else {
            for (int b = 0; b < B; b++)
                for (int o = tid; o < nfl; o += CTHREADS)
                    ofs[((size_t)b*A + a0)*42 + o] = 0.f;
        }
        return;
    }

    // ---- heavy path: stage gt xy (+zero row) ----
    for (int i = tid; i < ng + 42; i += CTHREADS) {
        float v = 0.f;
        if (i < ng) {
            int b2 = i / 42, e = i - b2*42;
            v = gt[b2*63 + 3*(e>>1) + (e&1)];
        }
        sg[i] = v;
    }
    __syncthreads();

    // ---- labels ----
    if (aligned4 && cnt == CTILE) {
        const int lf4 = (CTILE*3) >> 2;          // 48
        for (int idx = tid; idx < B*lf4; idx += CTHREADS) {
            int b = idx / lf4, f = idx - b*lf4;
            int o = f << 2;
            float4 v;
            float* vv = &v.x;
            int la = o / 3, c = o - la*3;
            #pragma unroll
            for (int i = 0; i < 4; i++) {
                int d = sdw[b*CTILE + la] >> 12;
                float val;
                if (d == 3) val = -1.f;
                else {
                    int want = (c == 0) ? 1 : (c == 2) ? 2 : 0;
                    val = (d == want) ? 1.f : 0.f;
                }
                vv[i] = val;
                if (++c == 3) { c = 0; ++la; }
            }
            __stcs((float4*)(labels + ((size_t)b*A + a0)*3) + f, v);
        }
    } else {
        for (int idx = tid; idx < B*cnt*3; idx += CTHREADS) {
            int b = idx / (cnt*3), o = idx - b*(cnt*3);
            int la = o / 3, c = o - la*3;
            int d = sdw[b*CTILE + la] >> 12;
            float val;
            if (d == 3) val = -1.f;
            else {
                int want = (c == 0) ? 1 : (c == 2) ? 2 : 0;
                val = (d == want) ? 1.f : 0.f;
            }
            labels[((size_t)b*A + a0)*3 + o] = val;
        }
    }

    // ---- offsets ----
    for (int f = tid; f < nf4; f += CTHREADS) {
        int o   = f << 2;
        int la0 = o / 42;
        int e0  = o - la0*42;
        int la3 = (o + 3) / 42;
        bool crossed = (la3 != la0);
        int e1 = e0 + 1, e2 = e0 + 2, e3 = e0 + 3;
        bool c1 = (e1 >= 42), c2 = (e2 >= 42), c3 = (e3 >= 42);
        if (c1) e1 -= 42;
        if (c2) e2 -= 42;
        if (c3) e3 -= 42;

        float4 av = ((const float4*)sA)[f];
        float4 vneg = make_float4(-av.x, -av.y, -av.z, -av.w);
        float4* op = (float4*)(ofs + (size_t)a0*42) + f;

        for (int b = 0; b < B; b++) {
            if (s_allneg[b]) {
                __stcs(op, vneg);
                op += bstride4;
                continue;
            }
            int base = b * CTILE;
            unsigned p0 = sdw[base + la0];
            unsigned p1 = crossed ? (unsigned)sdw[base + la3] : p0;
            int   r0 = p0 & 0xFFF;
            int   r1 = p1 & 0xFFF;
            bool  z0 = (p0 >> 12) == 3;
            bool  z1 = (p1 >> 12) == 3;

            float4 v;
            v.x = z0 ? 0.f : (sg[r0 + e0] - av.x);
            v.y = (c1 ? z1 : z0) ? 0.f : (sg[(c1 ? r1 : r0) + e1] - av.y);
            v.z = (c2 ? z1 : z0) ? 0.f : (sg[(c2 ? r1 : r0) + e2] - av.z);
            v.w = (c3 ? z1 : z0) ? 0.f : (sg[(c3 ? r1 : r0) + e3] - av.w);
            __stcs(op, v);
            op += bstride4;
        }
    }
    for (int o = (nf4 << 2) + tid; o < nfl; o += CTHREADS) {
        int la = o / 42, e = o - la*42;
        float av = sA[o];
        for (int b = 0; b < B; b++) {
            unsigned p = sdw[b*CTILE + la];
            int r = p & 0xFFF;
            float v = ((p >> 12) == 3) ? 0.f : (sg[r + e] - av);
            ofs[((size_t)b*A + a0)*42 + o] = v;
        }
    }
}

extern "C" void kernel_launch(void* const* d_in, const int* in_sizes, int n_in,
                              void* d_out, int out_size)
{
    const float* gt = (const float*)d_in[0];
    const int*   ht = (const int*)d_in[1];
    const int*   fh = (n_in >= 4) ? (const int*)d_in[2] : nullptr;
    const int*   fw = (n_in >= 4) ? (const int*)d_in[3] : nullptr;
    float* out = (float*)d_out;

    int B = in_sizes[0] / (2*NKPT*3);
    if (B < 1) B = 1;
    if (B > BMAX) B = BMAX;
    long long denom = 42 + 1 + 3LL*B + 42LL*B;
    int A = (int)((long long)out_size / denom);

    dim3 gridA((A + 127) / 128, (B + BSPLIT - 1) / BSPLIT);
    phaseA_kernel<<<gridA, 128>>>(gt, ht, fh, fw, B, A);

    float* anchors_out = out;
    float* inside_out  = out + (size_t)A*42;
    float* labels      = out + (size_t)A*43;
    float* ofs         = labels + (size_t)3*B*A;
    int aligned4  = ((A & 3) == 0) ? 1 : 0;
    int blocksC = (A + CTILE - 1) / CTILE;
    phaseC_kernel<<<blocksC, CTHREADS>>>(gt, fh, fw, anchors_out, inside_out,
                                         labels, ofs, A, B, aligned4);
}